// round 1
// baseline (speedup 1.0000x reference)
#include <cuda_runtime.h>

// Problem dims
#define BB 8
#define CC 16
#define PP 512
#define DD 1024
#define GG 512
#define MM (CC*PP)   // 8192 rows per batch

// Scratch: qg (post-relu) and per-row inverse L1 norms
__device__ float g_qg[(size_t)BB * MM * GG];   // 134 MB
__device__ float g_inv[BB * MM];

__device__ __forceinline__ float to_tf32(float x) {
    float y;
    asm("cvt.rna.tf32.f32 %0, %1;" : "=f"(y) : "f"(x));
    return y;
}

__device__ __forceinline__ void mma8(float c[4], const float a[4], const float b[2]) {
    asm volatile(
        "mma.sync.aligned.m16n8k8.row.col.f32.tf32.tf32.f32 "
        "{%0,%1,%2,%3}, {%4,%5,%6,%7}, {%8,%9}, {%0,%1,%2,%3};"
        : "+f"(c[0]), "+f"(c[1]), "+f"(c[2]), "+f"(c[3])
        : "f"(a[0]), "f"(a[1]), "f"(a[2]), "f"(a[3]), "f"(b[0]), "f"(b[1]));
}

// ============================================================================
// Kernel 1: qg[b,m,n] = relu( sum_k qz[b,m,k] * W[b,n,k] )    (NT GEMM)
// CTA tile 128x128, K-step 32, 8 warps (warp tile 32x64), double-buffered smem.
// Both A and B tiles are K-major -> smem stride 36 (conflict-free fragments).
// ============================================================================
__global__ __launch_bounds__(256) void qg_gemm_kernel(
    const float* __restrict__ qz, const float* __restrict__ W)
{
    constexpr int BM = 128, BN = 128, BK = 32, SA = 36;
    extern __shared__ float sm[];
    float* As = sm;                 // 2 * BM*SA
    float* Bs = sm + 2 * BM * SA;   // 2 * BN*SA

    const int t    = threadIdx.x;
    const int lane = t & 31, w = t >> 5;
    const int gid  = lane >> 2, tig = lane & 3;
    const int warp_m = (w & 3) * 32;
    const int warp_n = (w >> 2) * 64;
    const int bm = blockIdx.x * BM, bn = blockIdx.y * BN, b = blockIdx.z;

    const float* Ag = qz + ((size_t)b * MM + bm) * DD;
    const float* Bg = W  + ((size_t)b * GG + bn) * DD;

    float acc[2][8][4];
#pragma unroll
    for (int i = 0; i < 2; i++)
#pragma unroll
        for (int j = 0; j < 8; j++)
#pragma unroll
            for (int k = 0; k < 4; k++) acc[i][j][k] = 0.f;

    float4 ar[4], br[4];

    auto LOAD = [&](int k0) {
#pragma unroll
        for (int i = 0; i < 4; i++) {
            int idx = i * 256 + t;
            int row = idx >> 3, c4 = (idx & 7) * 4;
            ar[i] = *(const float4*)(Ag + (size_t)row * DD + k0 + c4);
            br[i] = *(const float4*)(Bg + (size_t)row * DD + k0 + c4);
        }
    };
    auto STORE = [&](int buf) {
        float* a   = As + buf * BM * SA;
        float* bsh = Bs + buf * BN * SA;
#pragma unroll
        for (int i = 0; i < 4; i++) {
            int idx = i * 256 + t;
            int row = idx >> 3, c4 = (idx & 7) * 4;
            float4 v = ar[i];
            v.x = to_tf32(v.x); v.y = to_tf32(v.y);
            v.z = to_tf32(v.z); v.w = to_tf32(v.w);
            *(float4*)(a + row * SA + c4) = v;
            v = br[i];
            v.x = to_tf32(v.x); v.y = to_tf32(v.y);
            v.z = to_tf32(v.z); v.w = to_tf32(v.w);
            *(float4*)(bsh + row * SA + c4) = v;
        }
    };
    auto COMP = [&](int buf) {
        const float* a   = As + buf * BM * SA;
        const float* bsh = Bs + buf * BN * SA;
#pragma unroll
        for (int kb = 0; kb < BK; kb += 8) {
            float bf[8][2];
#pragma unroll
            for (int nf = 0; nf < 8; nf++) {
                int n0 = warp_n + nf * 8 + gid;
                bf[nf][0] = bsh[n0 * SA + kb + tig];
                bf[nf][1] = bsh[n0 * SA + kb + tig + 4];
            }
#pragma unroll
            for (int mf = 0; mf < 2; mf++) {
                float av[4];
                int m0 = warp_m + mf * 16 + gid;
                av[0] = a[m0 * SA + kb + tig];
                av[1] = a[(m0 + 8) * SA + kb + tig];
                av[2] = a[m0 * SA + kb + tig + 4];
                av[3] = a[(m0 + 8) * SA + kb + tig + 4];
#pragma unroll
                for (int nf = 0; nf < 8; nf++) mma8(acc[mf][nf], av, bf[nf]);
            }
        }
    };

    LOAD(0); STORE(0); __syncthreads();
    const int NK = DD / BK;
    for (int it = 0; it < NK; ++it) {
        if (it + 1 < NK) LOAD((it + 1) * BK);
        COMP(it & 1);
        if (it + 1 < NK) {
            __syncthreads();
            STORE((it + 1) & 1);
            __syncthreads();
        }
    }

    // Epilogue: relu + store to scratch
    float* Cg = g_qg + ((size_t)b * MM + bm) * GG + bn;
#pragma unroll
    for (int mf = 0; mf < 2; mf++) {
        int r0 = warp_m + mf * 16 + gid;
#pragma unroll
        for (int nf = 0; nf < 8; nf++) {
            int c0 = warp_n + nf * 8 + tig * 2;
            float2 v0 = make_float2(fmaxf(acc[mf][nf][0], 0.f), fmaxf(acc[mf][nf][1], 0.f));
            float2 v1 = make_float2(fmaxf(acc[mf][nf][2], 0.f), fmaxf(acc[mf][nf][3], 0.f));
            *(float2*)(Cg + (size_t)r0 * GG + c0)       = v0;
            *(float2*)(Cg + (size_t)(r0 + 8) * GG + c0) = v1;
        }
    }
}

// ============================================================================
// Kernel 1b: per-row inverse L1 norm (one warp per row of 512 floats)
// ============================================================================
__global__ __launch_bounds__(256) void rowsum_kernel()
{
    int row  = blockIdx.x * 8 + (threadIdx.x >> 5);
    int lane = threadIdx.x & 31;
    const float4* p = (const float4*)(g_qg + (size_t)row * GG);
    float s = 0.f;
#pragma unroll
    for (int i = 0; i < 4; i++) {
        float4 v = p[lane + i * 32];
        s += (v.x + v.y) + (v.z + v.w);
    }
#pragma unroll
    for (int o = 16; o; o >>= 1) s += __shfl_xor_sync(0xffffffffu, s, o);
    if (lane == 0) g_inv[row] = 1.f / fmaxf(s, 1e-6f);
}

// ============================================================================
// Kernel 2: msg[b,m,n] = inv[b,m] * sum_k qg[b,m,k] * W[b,k,n]   (NN GEMM)
// A (qg) K-major smem stride 36; B (W) N-major smem stride 136 (both
// conflict-free). Row normalization folded into the epilogue.
// ============================================================================
__global__ __launch_bounds__(256) void msg_gemm_kernel(
    const float* __restrict__ W, float* __restrict__ out)
{
    constexpr int BM = 128, BN = 128, BK = 32, SA = 36, SB = 136;
    extern __shared__ float sm[];
    float* As = sm;                 // 2 * BM*SA
    float* Bs = sm + 2 * BM * SA;   // 2 * BK*SB

    const int t    = threadIdx.x;
    const int lane = t & 31, w = t >> 5;
    const int gid  = lane >> 2, tig = lane & 3;
    const int warp_m = (w & 3) * 32;
    const int warp_n = (w >> 2) * 64;
    const int bm = blockIdx.x * BM, bn = blockIdx.y * BN, b = blockIdx.z;

    const float* Ag = g_qg + ((size_t)b * MM + bm) * GG;
    const float* Bg = W + (size_t)b * GG * DD + bn;

    float acc[2][8][4];
#pragma unroll
    for (int i = 0; i < 2; i++)
#pragma unroll
        for (int j = 0; j < 8; j++)
#pragma unroll
            for (int k = 0; k < 4; k++) acc[i][j][k] = 0.f;

    float4 ar[4], br[4];

    auto LOAD = [&](int k0) {
#pragma unroll
        for (int i = 0; i < 4; i++) {
            int idx = i * 256 + t;
            int arow = idx >> 3, ac4 = (idx & 7) * 4;
            ar[i] = *(const float4*)(Ag + (size_t)arow * GG + k0 + ac4);
            int brow = idx >> 5, bc4 = (idx & 31) * 4;
            br[i] = *(const float4*)(Bg + (size_t)(k0 + brow) * DD + bc4);
        }
    };
    auto STORE = [&](int buf) {
        float* a   = As + buf * BM * SA;
        float* bsh = Bs + buf * BK * SB;
#pragma unroll
        for (int i = 0; i < 4; i++) {
            int idx = i * 256 + t;
            int arow = idx >> 3, ac4 = (idx & 7) * 4;
            float4 v = ar[i];
            v.x = to_tf32(v.x); v.y = to_tf32(v.y);
            v.z = to_tf32(v.z); v.w = to_tf32(v.w);
            *(float4*)(a + arow * SA + ac4) = v;
            int brow = idx >> 5, bc4 = (idx & 31) * 4;
            v = br[i];
            v.x = to_tf32(v.x); v.y = to_tf32(v.y);
            v.z = to_tf32(v.z); v.w = to_tf32(v.w);
            *(float4*)(bsh + brow * SB + bc4) = v;
        }
    };
    auto COMP = [&](int buf) {
        const float* a   = As + buf * BM * SA;
        const float* bsh = Bs + buf * BK * SB;
#pragma unroll
        for (int kb = 0; kb < BK; kb += 8) {
            float bf[8][2];
#pragma unroll
            for (int nf = 0; nf < 8; nf++) {
                int n0 = warp_n + nf * 8 + gid;
                bf[nf][0] = bsh[(kb + tig) * SB + n0];
                bf[nf][1] = bsh[(kb + tig + 4) * SB + n0];
            }
#pragma unroll
            for (int mf = 0; mf < 2; mf++) {
                float av[4];
                int m0 = warp_m + mf * 16 + gid;
                av[0] = a[m0 * SA + kb + tig];
                av[1] = a[(m0 + 8) * SA + kb + tig];
                av[2] = a[m0 * SA + kb + tig + 4];
                av[3] = a[(m0 + 8) * SA + kb + tig + 4];
#pragma unroll
                for (int nf = 0; nf < 8; nf++) mma8(acc[mf][nf], av, bf[nf]);
            }
        }
    };

    LOAD(0); STORE(0); __syncthreads();
    const int NK = GG / BK;
    for (int it = 0; it < NK; ++it) {
        if (it + 1 < NK) LOAD((it + 1) * BK);
        COMP(it & 1);
        if (it + 1 < NK) {
            __syncthreads();
            STORE((it + 1) & 1);
            __syncthreads();
        }
    }

    // Epilogue: scale each row by its inverse L1 norm, store fp32
    float* Cg = out + ((size_t)b * MM + bm) * DD + bn;
#pragma unroll
    for (int mf = 0; mf < 2; mf++) {
        int r0 = warp_m + mf * 16 + gid;
        float i0 = g_inv[b * MM + bm + r0];
        float i1 = g_inv[b * MM + bm + r0 + 8];
#pragma unroll
        for (int nf = 0; nf < 8; nf++) {
            int c0 = warp_n + nf * 8 + tig * 2;
            float2 v0 = make_float2(acc[mf][nf][0] * i0, acc[mf][nf][1] * i0);
            float2 v1 = make_float2(acc[mf][nf][2] * i1, acc[mf][nf][3] * i1);
            *(float2*)(Cg + (size_t)r0 * DD + c0)       = v0;
            *(float2*)(Cg + (size_t)(r0 + 8) * DD + c0) = v1;
        }
    }
}

extern "C" void kernel_launch(void* const* d_in, const int* in_sizes, int n_in,
                              void* d_out, int out_size)
{
    const float* qz = (const float*)d_in[0];
    const float* W  = (const float*)d_in[1];
    float* out = (float*)d_out;

    constexpr int SMEM1 = 2 * 128 * 36 * 4 + 2 * 128 * 36 * 4;  // 73728 B
    constexpr int SMEM2 = 2 * 128 * 36 * 4 + 2 * 32 * 136 * 4;  // 71680 B
    cudaFuncSetAttribute(qg_gemm_kernel,  cudaFuncAttributeMaxDynamicSharedMemorySize, SMEM1);
    cudaFuncSetAttribute(msg_gemm_kernel, cudaFuncAttributeMaxDynamicSharedMemorySize, SMEM2);

    dim3 g1(MM / 128, GG / 128, BB);
    qg_gemm_kernel<<<g1, 256, SMEM1>>>(qz, W);

    rowsum_kernel<<<(BB * MM) / 8, 256>>>();

    dim3 g2(MM / 128, DD / 128, BB);
    msg_gemm_kernel<<<g2, 256, SMEM2>>>(W, out);
}

// round 3
// speedup vs baseline: 1.5791x; 1.5791x over previous
#include <cuda_runtime.h>
#include <cstdint>

#define BB 8
#define MM 8192
#define DD 1024
#define GG 512

// Scratch
__device__ float g_qg[(size_t)BB * MM * GG];   // 134 MB: relu(qz @ W^T), unnormalized
__device__ float g_Wt[(size_t)BB * DD * GG];   // 16.8 MB: W transposed to [b, d, g]
__device__ float g_inv[BB * MM];               // per-row 1/max(L1,eps)

__device__ __forceinline__ float to_tf32(float x) {
    float y; asm("cvt.rna.tf32.f32 %0,%1;" : "=f"(y) : "f"(x)); return y;
}

__device__ __forceinline__ void ldsm4(uint32_t r[4], uint32_t addr) {
    asm volatile("ldmatrix.sync.aligned.m8n8.x4.shared.b16 {%0,%1,%2,%3}, [%4];"
        : "=r"(r[0]), "=r"(r[1]), "=r"(r[2]), "=r"(r[3]) : "r"(addr));
}

__device__ __forceinline__ void mma8(float c[4], const uint32_t a[4],
                                     uint32_t b0, uint32_t b1) {
    asm volatile(
        "mma.sync.aligned.m16n8k8.row.col.f32.tf32.tf32.f32 "
        "{%0,%1,%2,%3},{%4,%5,%6,%7},{%8,%9},{%0,%1,%2,%3};"
        : "+f"(c[0]), "+f"(c[1]), "+f"(c[2]), "+f"(c[3])
        : "r"(a[0]), "r"(a[1]), "r"(a[2]), "r"(a[3]), "r"(b0), "r"(b1));
}

__device__ __forceinline__ uint32_t smem_u32(const void* p) {
    uint32_t a;
    asm("{ .reg .u64 t; cvta.to.shared.u64 t, %1; cvt.u32.u64 %0, t; }" : "=r"(a) : "l"(p));
    return a;
}

// ---------------------------------------------------------------------------
// W transpose: g_Wt[b][d][g] = W[b][g][d]
// ---------------------------------------------------------------------------
__global__ __launch_bounds__(256) void transpose_W(const float* __restrict__ W) {
    __shared__ float t[32][33];
    int b = blockIdx.z;
    int d0 = blockIdx.x * 32, g0 = blockIdx.y * 32;
    int x = threadIdx.x & 31, y = threadIdx.x >> 5;
    const float* src = W + (size_t)b * GG * DD;
    float* dst = g_Wt + (size_t)b * DD * GG;
#pragma unroll
    for (int i = 0; i < 32; i += 8)
        t[y + i][x] = src[(size_t)(g0 + y + i) * DD + d0 + x];
    __syncthreads();
#pragma unroll
    for (int i = 0; i < 32; i += 8)
        dst[(size_t)(d0 + y + i) * GG + g0 + x] = t[x][y + i];
}

// ---------------------------------------------------------------------------
// NT GEMM via mma.sync.tf32 + ldmatrix fragments.
// C[128x128] = A[128 x KTOT] * B[128 x KTOT]^T, both operands K-major,
// smem tiles 128 rows x 32 floats with XOR-128B swizzle (conflict-free LDSM).
// EPI 0: relu, store to g_qg.   EPI 1: scale rows by g_inv, store to out.
// ---------------------------------------------------------------------------
template<int KTOT, int EPI>
__global__ __launch_bounds__(256) void gemm_ldsm(
    const float* __restrict__ Ain, const float* __restrict__ Bin,
    float* __restrict__ Cout)
{
    constexpr int BK = 32;
    constexpr int NK = KTOT / BK;
    constexpr int LDC = (EPI == 0) ? GG : DD;

    extern __shared__ __align__(128) char smem[];
    // A stages at 0 / 16K, B stages at 32K / 48K
    const uint32_t sb = smem_u32(smem);

    const int t    = threadIdx.x;
    const int lane = t & 31, w = t >> 5;
    const int gid  = lane >> 2, tig = lane & 3;
    const int warp_m = (w & 3) * 32;
    const int warp_n = (w >> 2) * 64;
    const int bm = blockIdx.x * 128, bn = blockIdx.y * 128, b = blockIdx.z;

    const float* Aall = (EPI == 0) ? Ain : g_qg;
    const float* Ball = (EPI == 0) ? Bin : g_Wt;
    float* Call = (EPI == 0) ? g_qg : Cout;

    const float* Ag = Aall + ((size_t)b * MM + bm) * KTOT;
    const float* Bg = Ball + ((size_t)b * LDC + bn) * KTOT;  // B rows: g (EPI0) / d (EPI1)
    float* Cg = Call + ((size_t)b * MM + bm) * LDC + bn;

    float acc[2][8][4];
#pragma unroll
    for (int i = 0; i < 2; i++)
#pragma unroll
        for (int j = 0; j < 8; j++)
#pragma unroll
            for (int k = 0; k < 4; k++) acc[i][j][k] = 0.f;

    float4 ar[4], br[4];

    auto LOAD = [&](int k0) {
#pragma unroll
        for (int j = 0; j < 4; j++) {
            int i = t + j * 256;
            int row = i >> 3, c4 = (i & 7) * 4;
            ar[j] = *(const float4*)(Ag + (size_t)row * KTOT + k0 + c4);
            br[j] = *(const float4*)(Bg + (size_t)row * KTOT + k0 + c4);
        }
    };
    auto STORE = [&](int buf) {
        char* a   = smem + buf * 16384;
        char* bsh = smem + 32768 + buf * 16384;
#pragma unroll
        for (int j = 0; j < 4; j++) {
            int i = t + j * 256;
            int row = i >> 3, g = i & 7;
            uint32_t off = (uint32_t)(row * 128) + (uint32_t)((g ^ (row & 7)) << 4);
            float4 v = ar[j];
            v.x = to_tf32(v.x); v.y = to_tf32(v.y);
            v.z = to_tf32(v.z); v.w = to_tf32(v.w);
            *(float4*)(a + off) = v;
            v = br[j];
            v.x = to_tf32(v.x); v.y = to_tf32(v.y);
            v.z = to_tf32(v.z); v.w = to_tf32(v.w);
            *(float4*)(bsh + off) = v;
        }
    };
    // ldmatrix lane-address components (constant across k-steps)
    const int mat   = lane >> 3;
    const int rsub  = (mat & 1) * 8 + (lane & 7);
    const int ghalf = mat >> 1;

    auto COMP = [&](int buf) {
        const uint32_t abase = sb + buf * 16384;
        const uint32_t bbase = sb + 32768 + buf * 16384;
#pragma unroll
        for (int ks = 0; ks < 4; ks++) {
            const int grp = 2 * ks + ghalf;
            uint32_t afr[2][4];
#pragma unroll
            for (int mf = 0; mf < 2; mf++) {
                int rr = warp_m + mf * 16 + rsub;
                ldsm4(afr[mf], abase + rr * 128 + ((grp ^ (rr & 7)) << 4));
            }
#pragma unroll
            for (int nb = 0; nb < 4; nb++) {
                uint32_t bfr[4];
                int rr = warp_n + nb * 16 + rsub;
                ldsm4(bfr, bbase + rr * 128 + ((grp ^ (rr & 7)) << 4));
#pragma unroll
                for (int mf = 0; mf < 2; mf++) {
                    mma8(acc[mf][2 * nb],     afr[mf], bfr[0], bfr[2]);
                    mma8(acc[mf][2 * nb + 1], afr[mf], bfr[1], bfr[3]);
                }
            }
        }
    };

    LOAD(0); STORE(0); __syncthreads();
    for (int it = 0; it < NK; ++it) {
        if (it + 1 < NK) LOAD((it + 1) * BK);
        COMP(it & 1);
        if (it + 1 < NK) {
            __syncthreads();
            STORE((it + 1) & 1);
            __syncthreads();
        }
    }

    // Epilogue
#pragma unroll
    for (int mf = 0; mf < 2; mf++) {
        int r0 = warp_m + mf * 16 + gid;
        float i0 = 1.f, i1 = 1.f;
        if (EPI == 1) {
            i0 = g_inv[b * MM + bm + r0];
            i1 = g_inv[b * MM + bm + r0 + 8];
        }
#pragma unroll
        for (int nf = 0; nf < 8; nf++) {
            int c0 = warp_n + nf * 8 + tig * 2;
            float2 v0, v1;
            if (EPI == 0) {
                v0 = make_float2(fmaxf(acc[mf][nf][0], 0.f), fmaxf(acc[mf][nf][1], 0.f));
                v1 = make_float2(fmaxf(acc[mf][nf][2], 0.f), fmaxf(acc[mf][nf][3], 0.f));
            } else {
                v0 = make_float2(acc[mf][nf][0] * i0, acc[mf][nf][1] * i0);
                v1 = make_float2(acc[mf][nf][2] * i1, acc[mf][nf][3] * i1);
            }
            *(float2*)(Cg + (size_t)r0 * LDC + c0)       = v0;
            *(float2*)(Cg + (size_t)(r0 + 8) * LDC + c0) = v1;
        }
    }
}

// ---------------------------------------------------------------------------
// Per-row inverse L1 norm (one warp per row of 512 floats)
// ---------------------------------------------------------------------------
__global__ __launch_bounds__(256) void rowsum_kernel()
{
    int row  = blockIdx.x * 8 + (threadIdx.x >> 5);
    int lane = threadIdx.x & 31;
    const float4* p = (const float4*)(g_qg + (size_t)row * GG);
    float s = 0.f;
#pragma unroll
    for (int i = 0; i < 4; i++) {
        float4 v = p[lane + i * 32];
        s += (v.x + v.y) + (v.z + v.w);
    }
#pragma unroll
    for (int o = 16; o; o >>= 1) s += __shfl_xor_sync(0xffffffffu, s, o);
    if (lane == 0) g_inv[row] = 1.f / fmaxf(s, 1e-6f);
}

// ---------------------------------------------------------------------------
extern "C" void kernel_launch(void* const* d_in, const int* in_sizes, int n_in,
                              void* d_out, int out_size)
{
    const float* qz = (const float*)d_in[0];
    const float* W  = (const float*)d_in[1];
    float* out = (float*)d_out;

    constexpr int SMEM = 65536;  // 2 stages x (16KB A + 16KB B)
    cudaFuncSetAttribute(gemm_ldsm<1024, 0>, cudaFuncAttributeMaxDynamicSharedMemorySize, SMEM);
    cudaFuncSetAttribute(gemm_ldsm<512, 1>,  cudaFuncAttributeMaxDynamicSharedMemorySize, SMEM);

    transpose_W<<<dim3(DD / 32, GG / 32, BB), 256>>>(W);

    // qg = relu(qz @ W^T)  [K = 1024]
    gemm_ldsm<1024, 0><<<dim3(MM / 128, GG / 128, BB), 256, SMEM>>>(qz, W, nullptr);

    rowsum_kernel<<<(BB * MM) / 8, 256>>>();

    // msg = (qg / L1) @ W  via Wt  [K = 512], scale folded into epilogue
    gemm_ldsm<512, 1><<<dim3(MM / 128, DD / 128, BB), 256, SMEM>>>(nullptr, nullptr, out);
}

// round 4
// speedup vs baseline: 1.7326x; 1.0972x over previous
#include <cuda_runtime.h>
#include <cstdint>

#define BB 8
#define MM 8192
#define DD 1024
#define GG 512

// Scratch
__device__ float g_qg[(size_t)BB * MM * GG];   // 134 MB: tf32-rounded relu(qz @ W^T)
__device__ float g_Wr[(size_t)BB * GG * DD];   // 16.8 MB: tf32-rounded W [b,g,d]
__device__ float g_Wt[(size_t)BB * DD * GG];   // 16.8 MB: tf32-rounded W^T [b,d,g]
__device__ float g_inv[BB * MM];               // per-row 1/max(L1,eps)

__device__ __forceinline__ float to_tf32(float x) {
    float y; asm("cvt.rna.tf32.f32 %0,%1;" : "=f"(y) : "f"(x)); return y;
}
__device__ __forceinline__ void ldsm4(uint32_t r[4], uint32_t addr) {
    asm volatile("ldmatrix.sync.aligned.m8n8.x4.shared.b16 {%0,%1,%2,%3}, [%4];"
        : "=r"(r[0]), "=r"(r[1]), "=r"(r[2]), "=r"(r[3]) : "r"(addr));
}
__device__ __forceinline__ void mma8(float c[4], const uint32_t a[4],
                                     uint32_t b0, uint32_t b1) {
    asm volatile(
        "mma.sync.aligned.m16n8k8.row.col.f32.tf32.tf32.f32 "
        "{%0,%1,%2,%3},{%4,%5,%6,%7},{%8,%9},{%0,%1,%2,%3};"
        : "+f"(c[0]), "+f"(c[1]), "+f"(c[2]), "+f"(c[3])
        : "r"(a[0]), "r"(a[1]), "r"(a[2]), "r"(a[3]), "r"(b0), "r"(b1));
}
__device__ __forceinline__ uint32_t smem_u32(const void* p) {
    uint32_t a;
    asm("{ .reg .u64 t; cvta.to.shared.u64 t, %1; cvt.u32.u64 %0, t; }" : "=r"(a) : "l"(p));
    return a;
}
#define CPA(dst, src) \
    asm volatile("cp.async.cg.shared.global [%0], [%1], 16;" :: "r"(dst), "l"(src) : "memory")
#define CPA_COMMIT() asm volatile("cp.async.commit_group;" ::: "memory")
#define CPA_WAIT(n)  asm volatile("cp.async.wait_group %0;" :: "n"(n) : "memory")

// ---------------------------------------------------------------------------
// W pre-rounding kernels
// ---------------------------------------------------------------------------
__global__ __launch_bounds__(256) void round_W(const float* __restrict__ W) {
    size_t i = ((size_t)blockIdx.x * 256 + threadIdx.x) * 4;
    float4 v = *(const float4*)(W + i);
    v.x = to_tf32(v.x); v.y = to_tf32(v.y); v.z = to_tf32(v.z); v.w = to_tf32(v.w);
    *(float4*)(g_Wr + i) = v;
}
__global__ __launch_bounds__(256) void transpose_W(const float* __restrict__ W) {
    __shared__ float t[32][33];
    int b = blockIdx.z;
    int d0 = blockIdx.x * 32, g0 = blockIdx.y * 32;
    int x = threadIdx.x & 31, y = threadIdx.x >> 5;
    const float* src = W + (size_t)b * GG * DD;
    float* dst = g_Wt + (size_t)b * DD * GG;
#pragma unroll
    for (int i = 0; i < 32; i += 8)
        t[y + i][x] = to_tf32(src[(size_t)(g0 + y + i) * DD + d0 + x]);
    __syncthreads();
#pragma unroll
    for (int i = 0; i < 32; i += 8)
        dst[(size_t)(d0 + y + i) * GG + g0 + x] = t[x][y + i];
}

// ---------------------------------------------------------------------------
// NT GEMM: C[128x128] = A[128 x KTOT] * B[128 x KTOT]^T, K-major operands.
// 4 warps, warp tile 64x64, double-buffered, XOR-swizzled smem, ldmatrix.
// EPI 0: A = qz staged via regs (LDG+cvt+STS), B = g_Wr via cp.async;
//        epilogue: relu + tf32 round -> g_qg.
// EPI 1: A = g_qg, B = g_Wt, both cp.async (pre-rounded);
//        epilogue: scale rows by g_inv -> out.
// ---------------------------------------------------------------------------
template<int KTOT, int EPI>
__global__ __launch_bounds__(128) void gemm_v4(
    const float* __restrict__ Ain, float* __restrict__ Cout)
{
    constexpr int BK = 32;
    constexpr int NK = KTOT / BK;
    constexpr int LDC = (EPI == 0) ? GG : DD;

    extern __shared__ __align__(128) char smem[];
    const uint32_t sb = smem_u32(smem);   // A0@0 A1@16K B0@32K B1@48K

    const int t    = threadIdx.x;
    const int lane = t & 31, w = t >> 5;
    const int gid  = lane >> 2, tig = lane & 3;
    const int warp_m = (w & 1) * 64;
    const int warp_n = (w >> 1) * 64;
    const int bm = blockIdx.x * 128, bn = blockIdx.y * 128, b = blockIdx.z;

    const float* Ag = ((EPI == 0) ? Ain : g_qg) + ((size_t)b * MM + bm) * KTOT;
    const float* Bg = ((EPI == 0) ? g_Wr : g_Wt) + ((size_t)b * LDC + bn) * KTOT;
    float* Cg = ((EPI == 0) ? g_qg : Cout) + ((size_t)b * MM + bm) * LDC + bn;

    float acc[4][8][4];
#pragma unroll
    for (int i = 0; i < 4; i++)
#pragma unroll
        for (int j = 0; j < 8; j++)
#pragma unroll
            for (int k = 0; k < 4; k++) acc[i][j][k] = 0.f;

    // ---- async copy of a 128x32 tile (16KB): 8 x 16B per thread ----
    auto ISSUE_B = [&](int it) {
        const int k0 = it * BK;
        const uint32_t base = sb + 32768 + (it & 1) * 16384;
#pragma unroll
        for (int j = 0; j < 8; j++) {
            int i = t + j * 128, row = i >> 3, g = i & 7;
            uint32_t off = (uint32_t)(row * 128) + (uint32_t)((g ^ (row & 7)) << 4);
            CPA(base + off, Bg + (size_t)row * KTOT + k0 + g * 4);
        }
    };
    auto ISSUE_A = [&](int it) {   // EPI==1 only
        const int k0 = it * BK;
        const uint32_t base = sb + (it & 1) * 16384;
#pragma unroll
        for (int j = 0; j < 8; j++) {
            int i = t + j * 128, row = i >> 3, g = i & 7;
            uint32_t off = (uint32_t)(row * 128) + (uint32_t)((g ^ (row & 7)) << 4);
            CPA(base + off, Ag + (size_t)row * KTOT + k0 + g * 4);
        }
    };

    // ---- staged A path for EPI==0 (needs cvt) ----
    float4 ar[8];
    auto LOAD_A = [&](int it) {
        const int k0 = it * BK;
#pragma unroll
        for (int j = 0; j < 8; j++) {
            int i = t + j * 128, row = i >> 3, g = i & 7;
            ar[j] = *(const float4*)(Ag + (size_t)row * KTOT + k0 + g * 4);
        }
    };
    auto STORE_A = [&](int it) {
        char* base = smem + (it & 1) * 16384;
#pragma unroll
        for (int j = 0; j < 8; j++) {
            int i = t + j * 128, row = i >> 3, g = i & 7;
            uint32_t off = (uint32_t)(row * 128) + (uint32_t)((g ^ (row & 7)) << 4);
            float4 v = ar[j];
            v.x = to_tf32(v.x); v.y = to_tf32(v.y);
            v.z = to_tf32(v.z); v.w = to_tf32(v.w);
            *(float4*)(base + off) = v;
        }
    };

    // ldmatrix lane-address components
    const int mat   = lane >> 3;
    const int rsub  = (mat & 1) * 8 + (lane & 7);
    const int ghalf = mat >> 1;

    auto COMP = [&](int buf) {
        const uint32_t abase = sb + buf * 16384;
        const uint32_t bbase = sb + 32768 + buf * 16384;
#pragma unroll
        for (int ks = 0; ks < 4; ks++) {
            const int grp = 2 * ks + ghalf;
            uint32_t afr[4][4];
#pragma unroll
            for (int mf = 0; mf < 4; mf++) {
                int rr = warp_m + mf * 16 + rsub;
                ldsm4(afr[mf], abase + rr * 128 + ((grp ^ (rr & 7)) << 4));
            }
#pragma unroll
            for (int nb = 0; nb < 4; nb++) {
                uint32_t bfr[4];
                int rr = warp_n + nb * 16 + rsub;
                ldsm4(bfr, bbase + rr * 128 + ((grp ^ (rr & 7)) << 4));
#pragma unroll
                for (int mf = 0; mf < 4; mf++) {
                    mma8(acc[mf][2 * nb],     afr[mf], bfr[0], bfr[2]);
                    mma8(acc[mf][2 * nb + 1], afr[mf], bfr[1], bfr[3]);
                }
            }
        }
    };

    // ---- pipelined mainloop ----
    if (EPI == 0) {
        ISSUE_B(0); CPA_COMMIT();
        ISSUE_B(1); CPA_COMMIT();
        LOAD_A(0); STORE_A(0); LOAD_A(1);
    } else {
        ISSUE_A(0); ISSUE_B(0); CPA_COMMIT();
        ISSUE_A(1); ISSUE_B(1); CPA_COMMIT();
    }
#pragma unroll 1
    for (int it = 0; it < NK; ++it) {
        if (it == NK - 1) CPA_WAIT(0); else CPA_WAIT(1);
        __syncthreads();
        COMP(it & 1);
        __syncthreads();
        if (it + 2 < NK) {
            if (EPI == 0) { ISSUE_B(it + 2); }
            else          { ISSUE_A(it + 2); ISSUE_B(it + 2); }
            CPA_COMMIT();
        }
        if (EPI == 0) {
            if (it + 1 < NK) STORE_A(it + 1);
            if (it + 2 < NK) LOAD_A(it + 2);
        }
    }

    // ---- epilogue ----
#pragma unroll
    for (int mf = 0; mf < 4; mf++) {
        int r0 = warp_m + mf * 16 + gid;
        float i0 = 1.f, i1 = 1.f;
        if (EPI == 1) {
            i0 = g_inv[b * MM + bm + r0];
            i1 = g_inv[b * MM + bm + r0 + 8];
        }
#pragma unroll
        for (int nf = 0; nf < 8; nf++) {
            int c0 = warp_n + nf * 8 + tig * 2;
            float2 v0, v1;
            if (EPI == 0) {
                v0 = make_float2(to_tf32(fmaxf(acc[mf][nf][0], 0.f)),
                                 to_tf32(fmaxf(acc[mf][nf][1], 0.f)));
                v1 = make_float2(to_tf32(fmaxf(acc[mf][nf][2], 0.f)),
                                 to_tf32(fmaxf(acc[mf][nf][3], 0.f)));
            } else {
                v0 = make_float2(acc[mf][nf][0] * i0, acc[mf][nf][1] * i0);
                v1 = make_float2(acc[mf][nf][2] * i1, acc[mf][nf][3] * i1);
            }
            *(float2*)(Cg + (size_t)r0 * LDC + c0)       = v0;
            *(float2*)(Cg + (size_t)(r0 + 8) * LDC + c0) = v1;
        }
    }
}

// ---------------------------------------------------------------------------
// Per-row inverse L1 norm (one warp per row of 512 floats)
// ---------------------------------------------------------------------------
__global__ __launch_bounds__(256) void rowsum_kernel()
{
    int row  = blockIdx.x * 8 + (threadIdx.x >> 5);
    int lane = threadIdx.x & 31;
    const float4* p = (const float4*)(g_qg + (size_t)row * GG);
    float s = 0.f;
#pragma unroll
    for (int i = 0; i < 4; i++) {
        float4 v = p[lane + i * 32];
        s += (v.x + v.y) + (v.z + v.w);
    }
#pragma unroll
    for (int o = 16; o; o >>= 1) s += __shfl_xor_sync(0xffffffffu, s, o);
    if (lane == 0) g_inv[row] = 1.f / fmaxf(s, 1e-6f);
}

// ---------------------------------------------------------------------------
extern "C" void kernel_launch(void* const* d_in, const int* in_sizes, int n_in,
                              void* d_out, int out_size)
{
    const float* qz = (const float*)d_in[0];
    const float* W  = (const float*)d_in[1];
    float* out = (float*)d_out;

    constexpr int SMEM = 65536;  // 2 stages x (16KB A + 16KB B)
    cudaFuncSetAttribute(gemm_v4<1024, 0>, cudaFuncAttributeMaxDynamicSharedMemorySize, SMEM);
    cudaFuncSetAttribute(gemm_v4<512, 1>,  cudaFuncAttributeMaxDynamicSharedMemorySize, SMEM);

    round_W<<<(BB * GG * DD) / (256 * 4), 256>>>(W);
    transpose_W<<<dim3(DD / 32, GG / 32, BB), 256>>>(W);

    // qg = tf32(relu(qz @ W^T))  [K = 1024]
    gemm_v4<1024, 0><<<dim3(MM / 128, GG / 128, BB), 128, SMEM>>>(qz, nullptr);

    rowsum_kernel<<<(BB * MM) / 8, 256>>>();

    // msg = (qg / L1) @ W  via Wt  [K = 512], scale folded into epilogue
    gemm_v4<512, 1><<<dim3(MM / 128, DD / 128, BB), 128, SMEM>>>(nullptr, out);
}